// round 9
// baseline (speedup 1.0000x reference)
#include <cuda_runtime.h>

// ---------------------------------------------------------------------------
// 3-layer GRU + linear head. B=64, T=512, F=128, H=512, 3H=1536, O=128.
// ---------------------------------------------------------------------------
#define B_SZ   64
#define T_SZ   512
#define F_SZ   128
#define H_SZ   512
#define G3_SZ  1536
#define O_SZ   128
#define M_SZ   (B_SZ * T_SZ)

#define SCAN_NBLK  128

typedef unsigned long long u64;

__device__ __forceinline__ u64 splat2(float x) {
    u64 r; asm("mov.b64 %0, {%1, %1};" : "=l"(r) : "f"(x)); return r;
}
__device__ __forceinline__ void fma2(u64 &d, u64 a, u64 b) {
    asm("fma.rn.f32x2 %0, %1, %2, %0;" : "+l"(d) : "l"(a), "l"(b));
}
__device__ __forceinline__ float2 unpack2(u64 v) {
    float2 f; asm("mov.b64 {%0, %1}, %2;" : "=f"(f.x), "=f"(f.y) : "l"(v)); return f;
}
__device__ __forceinline__ unsigned ld_acq(const unsigned* p) {
    unsigned v; asm volatile("ld.global.acquire.gpu.u32 %0, [%1];" : "=r"(v) : "l"(p) : "memory"); return v;
}
__device__ __forceinline__ void st_rel(unsigned* p, unsigned v) {
    asm volatile("st.global.release.gpu.u32 [%0], %1;" :: "l"(p), "r"(v) : "memory");
}

// ---------------------------------------------------------------------------
// Scratch (device globals -- allocation-free per harness rules)
// ---------------------------------------------------------------------------
__device__ float    g_xp[(size_t)M_SZ * G3_SZ];
__device__ float    g_hseq[(size_t)M_SZ * H_SZ];
__device__ unsigned g_flags[4][32];   // per-block step counters; one line per group

// ---------------------------------------------------------------------------
// GEMM: C[M,N] = A[M,K] @ W[N,K]^T + bias[N].  128x128x16 tile, f32x2 FMA,
// register double-buffered gmem loads.  (R5 exact)
// ---------------------------------------------------------------------------
__global__ void __launch_bounds__(256)
gemm_bias_kernel(const float* __restrict__ A, const float* __restrict__ W,
                 const float* __restrict__ bias, float* __restrict__ C,
                 int M, int N, int K)
{
    __shared__ float As[16][132];
    __shared__ float Ws[16][132];

    const int tid = threadIdx.x;
    const int tx  = tid & 15;
    const int ty  = tid >> 4;
    const int m0  = blockIdx.y * 128;
    const int n0  = blockIdx.x * 128;

    u64 acc[8][4];
#pragma unroll
    for (int i = 0; i < 8; i++)
#pragma unroll
        for (int j = 0; j < 4; j++) acc[i][j] = 0ull;

    const int lr = tid >> 2;
    const int lk = (tid & 3) * 4;

    float4 pa[2], pw[2];
#pragma unroll
    for (int h = 0; h < 2; h++) {
        const int row = lr + h * 64;
        pa[h] = *(const float4*)(A + (size_t)(m0 + row) * K + lk);
        pw[h] = *(const float4*)(W + (size_t)(n0 + row) * K + lk);
    }

    for (int k0 = 0; k0 < K; k0 += 16) {
#pragma unroll
        for (int h = 0; h < 2; h++) {
            const int row = lr + h * 64;
            As[lk + 0][row] = pa[h].x; As[lk + 1][row] = pa[h].y;
            As[lk + 2][row] = pa[h].z; As[lk + 3][row] = pa[h].w;
            Ws[lk + 0][row] = pw[h].x; Ws[lk + 1][row] = pw[h].y;
            Ws[lk + 2][row] = pw[h].z; Ws[lk + 3][row] = pw[h].w;
        }
        __syncthreads();
        if (k0 + 16 < K) {
#pragma unroll
            for (int h = 0; h < 2; h++) {
                const int row = lr + h * 64;
                pa[h] = *(const float4*)(A + (size_t)(m0 + row) * K + k0 + 16 + lk);
                pw[h] = *(const float4*)(W + (size_t)(n0 + row) * K + k0 + 16 + lk);
            }
        }
#pragma unroll
        for (int k = 0; k < 16; k++) {
            float4 a0 = *(const float4*)&As[k][ty * 8];
            float4 a1 = *(const float4*)&As[k][ty * 8 + 4];
            ulonglong2 w01 = *(const ulonglong2*)&Ws[k][tx * 8];
            ulonglong2 w23 = *(const ulonglong2*)&Ws[k][tx * 8 + 4];
            float av[8] = {a0.x, a0.y, a0.z, a0.w, a1.x, a1.y, a1.z, a1.w};
#pragma unroll
            for (int i = 0; i < 8; i++) {
                u64 as = splat2(av[i]);
                fma2(acc[i][0], as, w01.x);
                fma2(acc[i][1], as, w01.y);
                fma2(acc[i][2], as, w23.x);
                fma2(acc[i][3], as, w23.y);
            }
        }
        __syncthreads();
    }

#pragma unroll
    for (int i = 0; i < 8; i++) {
        const int m = m0 + ty * 8 + i;
        float* crow = C + (size_t)m * N + n0 + tx * 8;
#pragma unroll
        for (int j = 0; j < 4; j++) {
            float2 v = unpack2(acc[i][j]);
            const int n = n0 + tx * 8 + j * 2;
            crow[j * 2 + 0] = v.x + bias[n + 0];
            crow[j * 2 + 1] = v.y + bias[n + 1];
        }
    }
}

// ---------------------------------------------------------------------------
// Persistent GRU scan. 128 blocks = 4 batch-groups x 32 j-tiles, 512 threads.
// jg = tid&7 (j pair), bg = (tid>>3)&3 (batch quad), ks = tid>>5 (warp id,
// k-split 16, 32 k's each). Micro-tile: 4b x 2j x 3g packed f32x2.
// FINE-GRAINED DATAFLOW: warp ks consumes h cols [ks*32, ks*32+32), produced
// by exactly blocks jt = 2ks and 2ks+1. Two lanes of each warp poll just
// those two flags, then the warp stages its slice and starts its dot —
// a slow producer delays one warp's tail, not the whole block's step.
// No leader/gen aggregation; publish = one st.release of the block's flag.
// ---------------------------------------------------------------------------
struct ScanSmem {
    float    ws[3][8][1028];   // [gate][jpair][k*2+p]
    float    hs[16][516];      // h_{t-1} tile
    float    red[512][26];     // 24 partials per thread, pitch 26
    float    bhs[48];
    unsigned baseu;
};

__global__ void __launch_bounds__(512, 1)
scan_kernel(const float* __restrict__ Whh, const float* __restrict__ bhh,
            const float* __restrict__ xp, float* __restrict__ hseq)
{
    extern __shared__ ScanSmem smem[];
    ScanSmem& s = smem[0];

    const int tid  = threadIdx.x;
    const int lane = tid & 31;
    const int jg   = tid & 7;
    const int bg   = (tid >> 3) & 3;
    const int ks   = tid >> 5;          // warp id; consumes h cols [ks*32,+32)
    const int bt   = blockIdx.x >> 5;
    const int jt   = blockIdx.x & 31;
    const int b0   = bt * 16;
    const int j0   = jt * 16;

    if (tid == 0) s.baseu = ld_acq(&g_flags[bt][jt]);   // launch base (uniform)

    // Resident weights: 48 rows x 512, pair-interleaved over j.
    for (int i = tid; i < 48 * 128; i += 512) {
        const int rl = i >> 7, k4 = i & 127;
        const int gg = rl >> 4, jj = rl & 15;
        float4 v = *(const float4*)(Whh + (size_t)(gg * H_SZ + j0 + jj) * H_SZ + k4 * 4);
        const int jp = jj >> 1, p = jj & 1;
        float* w = &s.ws[gg][jp][0];
        w[(k4 * 4 + 0) * 2 + p] = v.x;
        w[(k4 * 4 + 1) * 2 + p] = v.y;
        w[(k4 * 4 + 2) * 2 + p] = v.z;
        w[(k4 * 4 + 3) * 2 + p] = v.w;
    }
    if (tid < 48) s.bhs[tid] = bhh[(tid >> 4) * H_SZ + j0 + (tid & 15)];
    __syncthreads();

    const unsigned base_flag = s.baseu;

    // Warp-local staging geometry (16 rows x 32 cols per warp, 4 f4/lane).
    const int st_row = lane >> 3;             // + 4u
    const int st_col = ks * 32 + (lane & 7) * 4;

    // Finalizer identity (tid < 128): 1 batch x 2 j each.
    const int fb   = tid >> 5;
    const int fi5  = tid & 31;
    const int fbg  = fi5 >> 3;
    const int fjg  = fi5 & 7;
    const int fbl  = fbg * 4 + fb;
    const int fjl0 = fjg * 2;

    // xp prefetch for t = 0
    float2 xv[3];
    if (tid < 128) {
        const size_t row = ((size_t)(b0 + fbl) * T_SZ + 0) * G3_SZ;
#pragma unroll
        for (int g = 0; g < 3; g++)
            xv[g] = *(const float2*)(xp + row + g * H_SZ + j0 + fjl0);
    }

    for (int t = 0; t < T_SZ; t++) {
        // ---- per-warp producer poll + warp-local h staging
        if (t == 0) {
            const float4 z = make_float4(0.f, 0.f, 0.f, 0.f);
#pragma unroll
            for (int u = 0; u < 4; u++)
                *(float4*)&s.hs[st_row + 4 * u][st_col] = z;
        } else {
            if (lane < 2) {
                const unsigned tgt = base_flag + (unsigned)t;
                const unsigned* fp = &g_flags[bt][2 * ks + lane];
                while ((int)(ld_acq(fp) - tgt) < 0) { }
            }
            __syncwarp();
            float4 v[4];
#pragma unroll
            for (int u = 0; u < 4; u++)
                v[u] = *(const float4*)(hseq +
                        ((size_t)(b0 + st_row + 4 * u) * T_SZ + (t - 1)) * H_SZ + st_col);
#pragma unroll
            for (int u = 0; u < 4; u++)
                *(float4*)&s.hs[st_row + 4 * u][st_col] = v[u];
        }
        __syncwarp();

        // ---- partial dots: 4b x 2j x 3g over this warp's 32 k's
        u64 acc[4][3];
#pragma unroll
        for (int b = 0; b < 4; b++)
#pragma unroll
            for (int g = 0; g < 3; g++) acc[b][g] = 0ull;

        {
            const float* wr = &s.ws[0][jg][ks * 64];
            const float* wz = &s.ws[1][jg][ks * 64];
            const float* wn = &s.ws[2][jg][ks * 64];
            const float* hb = &s.hs[bg * 4][ks * 32];
#pragma unroll 2
            for (int c = 0; c < 8; c++) {
                ulonglong2 rA = *(const ulonglong2*)(wr + c * 8);
                ulonglong2 rB = *(const ulonglong2*)(wr + c * 8 + 4);
                ulonglong2 zA = *(const ulonglong2*)(wz + c * 8);
                ulonglong2 zB = *(const ulonglong2*)(wz + c * 8 + 4);
                ulonglong2 nA = *(const ulonglong2*)(wn + c * 8);
                ulonglong2 nB = *(const ulonglong2*)(wn + c * 8 + 4);
#pragma unroll
                for (int b = 0; b < 4; b++) {
                    float4 h = *(const float4*)(hb + b * 516 + c * 4);
                    u64 a0 = splat2(h.x), a1 = splat2(h.y);
                    u64 a2 = splat2(h.z), a3 = splat2(h.w);
                    fma2(acc[b][0], a0, rA.x); fma2(acc[b][0], a1, rA.y);
                    fma2(acc[b][0], a2, rB.x); fma2(acc[b][0], a3, rB.y);
                    fma2(acc[b][1], a0, zA.x); fma2(acc[b][1], a1, zA.y);
                    fma2(acc[b][1], a2, zB.x); fma2(acc[b][1], a3, zB.y);
                    fma2(acc[b][2], a0, nA.x); fma2(acc[b][2], a1, nA.y);
                    fma2(acc[b][2], a2, nB.x); fma2(acc[b][2], a3, nB.y);
                }
            }
        }

        // ---- write partials: [b][g][p] order, 12 x STS.64
        {
            float* rp = &s.red[tid][0];
#pragma unroll
            for (int b = 0; b < 4; b++)
#pragma unroll
                for (int g = 0; g < 3; g++)
                    *(float2*)(rp + b * 6 + g * 2) = unpack2(acc[b][g]);
        }
        __syncthreads();

        // ---- finalize: tid < 128, each 1 batch x 2 j; sum 16 k-slices
        if (tid < 128) {
            float2 t0 = make_float2(0.f, 0.f), t1 = t0, t2 = t0;
#pragma unroll
            for (int sdx = 0; sdx < 16; sdx++) {
                const float* rp = &s.red[sdx * 32 + fi5][fb * 6];
                float2 a = *(const float2*)(rp + 0);
                float2 b = *(const float2*)(rp + 2);
                float2 c = *(const float2*)(rp + 4);
                t0.x += a.x; t0.y += a.y;
                t1.x += b.x; t1.y += b.y;
                t2.x += c.x; t2.y += c.y;
            }
            float2 hv;
#pragma unroll
            for (int p = 0; p < 2; p++) {
                const int jl = fjl0 + p;
                float dr = (p == 0) ? t0.x : t0.y;
                float dz = (p == 0) ? t1.x : t1.y;
                float dn = (p == 0) ? t2.x : t2.y;
                float xr = (p == 0) ? xv[0].x : xv[0].y;
                float xz = (p == 0) ? xv[1].x : xv[1].y;
                float xn = (p == 0) ? xv[2].x : xv[2].y;
                float rg = 1.f / (1.f + __expf(-(xr + dr + s.bhs[jl])));
                float zg = 1.f / (1.f + __expf(-(xz + dz + s.bhs[16 + jl])));
                float ng = tanhf(xn + rg * (dn + s.bhs[32 + jl]));
                float hp = s.hs[fbl][j0 + jl];
                float h  = (1.f - zg) * ng + zg * hp;
                if (p == 0) hv.x = h; else hv.y = h;
            }
            *(float2*)(hseq + ((size_t)(b0 + fbl) * T_SZ + t) * H_SZ + j0 + fjl0) = hv;

            // prefetch xp for next step
            const int tn = (t + 1 < T_SZ) ? t + 1 : t;
            const size_t row = ((size_t)(b0 + fbl) * T_SZ + tn) * G3_SZ;
#pragma unroll
            for (int g = 0; g < 3; g++)
                xv[g] = *(const float2*)(xp + row + g * H_SZ + j0 + fjl0);
        }
        __syncthreads();   // h_t STGs issued; hs/red safe to reuse next iter

        // ---- publish own flag (one st.release; no aggregation hop)
        if (t + 1 < T_SZ && tid == 0)
            st_rel(&g_flags[bt][jt], base_flag + (unsigned)t + 1u);
    }
}

// ---------------------------------------------------------------------------
// Launch
// ---------------------------------------------------------------------------
extern "C" void kernel_launch(void* const* d_in, const int* in_sizes, int n_in,
                              void* d_out, int out_size)
{
    (void)in_sizes; (void)n_in; (void)out_size;
    const float* x    = (const float*)d_in[0];
    const float* Wih0 = (const float*)d_in[1];
    const float* Whh0 = (const float*)d_in[2];
    const float* bih0 = (const float*)d_in[3];
    const float* bhh0 = (const float*)d_in[4];
    const float* Wih1 = (const float*)d_in[5];
    const float* Whh1 = (const float*)d_in[6];
    const float* bih1 = (const float*)d_in[7];
    const float* bhh1 = (const float*)d_in[8];
    const float* Wih2 = (const float*)d_in[9];
    const float* Whh2 = (const float*)d_in[10];
    const float* bih2 = (const float*)d_in[11];
    const float* bhh2 = (const float*)d_in[12];
    const float* Wout = (const float*)d_in[13];
    const float* bout = (const float*)d_in[14];
    float* out = (float*)d_out;

    cudaFuncSetAttribute(scan_kernel, cudaFuncAttributeMaxDynamicSharedMemorySize,
                         (int)sizeof(ScanSmem));

    void *xp_v = nullptr, *hs_v = nullptr;
    cudaGetSymbolAddress(&xp_v, g_xp);
    cudaGetSymbolAddress(&hs_v, g_hseq);
    float* xpd = (float*)xp_v;
    float* hs  = (float*)hs_v;

    const dim3 gblk(256), sblk(512);
    const dim3 g_proj(G3_SZ / 128, M_SZ / 128);
    const dim3 g_head(O_SZ / 128,  M_SZ / 128);
    const size_t scan_smem = sizeof(ScanSmem);

    gemm_bias_kernel<<<g_proj, gblk>>>(x,  Wih0, bih0, xpd, M_SZ, G3_SZ, F_SZ);
    scan_kernel<<<SCAN_NBLK, sblk, scan_smem>>>(Whh0, bhh0, xpd, hs);
    gemm_bias_kernel<<<g_proj, gblk>>>(hs, Wih1, bih1, xpd, M_SZ, G3_SZ, H_SZ);
    scan_kernel<<<SCAN_NBLK, sblk, scan_smem>>>(Whh1, bhh1, xpd, hs);
    gemm_bias_kernel<<<g_proj, gblk>>>(hs, Wih2, bih2, xpd, M_SZ, G3_SZ, H_SZ);
    scan_kernel<<<SCAN_NBLK, sblk, scan_smem>>>(Whh2, bhh2, xpd, hs);
    gemm_bias_kernel<<<g_head, gblk>>>(hs, Wout, bout, out, M_SZ, O_SZ, H_SZ);
}

// round 10
// speedup vs baseline: 1.7762x; 1.7762x over previous
#include <cuda_runtime.h>

// ---------------------------------------------------------------------------
// 3-layer GRU + linear head. B=64, T=512, F=128, H=512, 3H=1536, O=128.
// ---------------------------------------------------------------------------
#define B_SZ   64
#define T_SZ   512
#define F_SZ   128
#define H_SZ   512
#define G3_SZ  1536
#define O_SZ   128
#define M_SZ   (B_SZ * T_SZ)

#define SCAN_NBLK  128

typedef unsigned long long u64;

__device__ __forceinline__ u64 splat2(float x) {
    u64 r; asm("mov.b64 %0, {%1, %1};" : "=l"(r) : "f"(x)); return r;
}
__device__ __forceinline__ void fma2(u64 &d, u64 a, u64 b) {
    asm("fma.rn.f32x2 %0, %1, %2, %0;" : "+l"(d) : "l"(a), "l"(b));
}
__device__ __forceinline__ float2 unpack2(u64 v) {
    float2 f; asm("mov.b64 {%0, %1}, %2;" : "=f"(f.x), "=f"(f.y) : "l"(v)); return f;
}
__device__ __forceinline__ unsigned ld_acq(const unsigned* p) {
    unsigned v; asm volatile("ld.global.acquire.gpu.u32 %0, [%1];" : "=r"(v) : "l"(p) : "memory"); return v;
}
__device__ __forceinline__ void st_rel(unsigned* p, unsigned v) {
    asm volatile("st.global.release.gpu.u32 [%0], %1;" :: "l"(p), "r"(v) : "memory");
}

// ---------------------------------------------------------------------------
// Scratch (device globals -- allocation-free per harness rules)
// ---------------------------------------------------------------------------
__device__ float    g_xp[(size_t)M_SZ * G3_SZ];
__device__ float    g_hseq[(size_t)M_SZ * H_SZ];
__device__ unsigned g_flags[4][32];   // per-block step counters; one line per group
__device__ unsigned g_genf[4][32];    // generation per group at [g][0]

// ---------------------------------------------------------------------------
// GEMM: C[M,N] = A[M,K] @ W[N,K]^T + bias[N].  128x128x16 tile, f32x2 FMA,
// register double-buffered gmem loads.  (R5 exact)
// ---------------------------------------------------------------------------
__global__ void __launch_bounds__(256)
gemm_bias_kernel(const float* __restrict__ A, const float* __restrict__ W,
                 const float* __restrict__ bias, float* __restrict__ C,
                 int M, int N, int K)
{
    __shared__ float As[16][132];
    __shared__ float Ws[16][132];

    const int tid = threadIdx.x;
    const int tx  = tid & 15;
    const int ty  = tid >> 4;
    const int m0  = blockIdx.y * 128;
    const int n0  = blockIdx.x * 128;

    u64 acc[8][4];
#pragma unroll
    for (int i = 0; i < 8; i++)
#pragma unroll
        for (int j = 0; j < 4; j++) acc[i][j] = 0ull;

    const int lr = tid >> 2;
    const int lk = (tid & 3) * 4;

    float4 pa[2], pw[2];
#pragma unroll
    for (int h = 0; h < 2; h++) {
        const int row = lr + h * 64;
        pa[h] = *(const float4*)(A + (size_t)(m0 + row) * K + lk);
        pw[h] = *(const float4*)(W + (size_t)(n0 + row) * K + lk);
    }

    for (int k0 = 0; k0 < K; k0 += 16) {
#pragma unroll
        for (int h = 0; h < 2; h++) {
            const int row = lr + h * 64;
            As[lk + 0][row] = pa[h].x; As[lk + 1][row] = pa[h].y;
            As[lk + 2][row] = pa[h].z; As[lk + 3][row] = pa[h].w;
            Ws[lk + 0][row] = pw[h].x; Ws[lk + 1][row] = pw[h].y;
            Ws[lk + 2][row] = pw[h].z; Ws[lk + 3][row] = pw[h].w;
        }
        __syncthreads();
        if (k0 + 16 < K) {
#pragma unroll
            for (int h = 0; h < 2; h++) {
                const int row = lr + h * 64;
                pa[h] = *(const float4*)(A + (size_t)(m0 + row) * K + k0 + 16 + lk);
                pw[h] = *(const float4*)(W + (size_t)(n0 + row) * K + k0 + 16 + lk);
            }
        }
#pragma unroll
        for (int k = 0; k < 16; k++) {
            float4 a0 = *(const float4*)&As[k][ty * 8];
            float4 a1 = *(const float4*)&As[k][ty * 8 + 4];
            ulonglong2 w01 = *(const ulonglong2*)&Ws[k][tx * 8];
            ulonglong2 w23 = *(const ulonglong2*)&Ws[k][tx * 8 + 4];
            float av[8] = {a0.x, a0.y, a0.z, a0.w, a1.x, a1.y, a1.z, a1.w};
#pragma unroll
            for (int i = 0; i < 8; i++) {
                u64 as = splat2(av[i]);
                fma2(acc[i][0], as, w01.x);
                fma2(acc[i][1], as, w01.y);
                fma2(acc[i][2], as, w23.x);
                fma2(acc[i][3], as, w23.y);
            }
        }
        __syncthreads();
    }

#pragma unroll
    for (int i = 0; i < 8; i++) {
        const int m = m0 + ty * 8 + i;
        float* crow = C + (size_t)m * N + n0 + tx * 8;
#pragma unroll
        for (int j = 0; j < 4; j++) {
            float2 v = unpack2(acc[i][j]);
            const int n = n0 + tx * 8 + j * 2;
            crow[j * 2 + 0] = v.x + bias[n + 0];
            crow[j * 2 + 1] = v.y + bias[n + 1];
        }
    }
}

// ---------------------------------------------------------------------------
// Persistent GRU scan. 128 blocks = 4 batch-groups x 32 j-tiles, 512 threads.
// jg = tid&7 (j pair), bg = (tid>>3)&3 (batch quad), ks = tid>>5 (warp id,
// k-split 16, 32 k's each). Micro-tile: 4b x 2j x 3g packed f32x2.
// R5 structure exactly, with two isolated deltas:
//  (i) warp-local h staging: warp ks stages only cols [ks*32, ks*32+32)
//      it consumes -> __syncwarp instead of a block-wide stage sync;
// (ii) publish+barrier skipped uniformly on the last step (bases are
//      own-flag / raw-gen reads; race-free since gen(t=1) cannot publish
//      before every block has passed step 0, hence read its bases).
// Barrier: R5 two-hop (leader warp polls 32 flags; others spin one gen word).
// ---------------------------------------------------------------------------
struct ScanSmem {
    float    ws[3][8][1028];   // [gate][jpair][k*2+p]
    float    hs[16][516];      // h_{t-1} tile
    float    red[512][26];     // 24 partials per thread, pitch 26 (2-way max)
    float    bhs[48];
    unsigned baseu[2];
};

__global__ void __launch_bounds__(512, 1)
scan_kernel(const float* __restrict__ Whh, const float* __restrict__ bhh,
            const float* __restrict__ xp, float* __restrict__ hseq)
{
    extern __shared__ ScanSmem smem[];
    ScanSmem& s = smem[0];

    const int tid  = threadIdx.x;
    const int lane = tid & 31;
    const int jg   = tid & 7;
    const int bg   = (tid >> 3) & 3;
    const int ks   = tid >> 5;          // warp id; consumes h cols [ks*32,+32)
    const int bt   = blockIdx.x >> 5;
    const int jt   = blockIdx.x & 31;
    const int b0   = bt * 16;
    const int j0   = jt * 16;

    if (tid == 0) {
        s.baseu[0] = ld_acq(&g_flags[bt][jt]);   // own flag: uniform across group
        s.baseu[1] = ld_acq(&g_genf[bt][0]);
    }

    // Resident weights: 48 rows x 512, pair-interleaved over j.
    for (int i = tid; i < 48 * 128; i += 512) {
        const int rl = i >> 7, k4 = i & 127;
        const int gg = rl >> 4, jj = rl & 15;
        float4 v = *(const float4*)(Whh + (size_t)(gg * H_SZ + j0 + jj) * H_SZ + k4 * 4);
        const int jp = jj >> 1, p = jj & 1;
        float* w = &s.ws[gg][jp][0];
        w[(k4 * 4 + 0) * 2 + p] = v.x;
        w[(k4 * 4 + 1) * 2 + p] = v.y;
        w[(k4 * 4 + 2) * 2 + p] = v.z;
        w[(k4 * 4 + 3) * 2 + p] = v.w;
    }
    if (tid < 48) s.bhs[tid] = bhh[(tid >> 4) * H_SZ + j0 + (tid & 15)];
    __syncthreads();

    const unsigned base_flag = s.baseu[0];
    const unsigned base_gen  = s.baseu[1];

    // Warp-local staging geometry (16 rows x 32 cols per warp, 4 f4/lane).
    const int st_row = lane >> 3;             // + 4u, u = 0..3
    const int st_col = ks * 32 + (lane & 7) * 4;

    // Finalizer identity (tid < 128): 1 batch x 2 j each.
    const int fb   = tid >> 5;
    const int fi5  = tid & 31;
    const int fbg  = fi5 >> 3;
    const int fjg  = fi5 & 7;
    const int fbl  = fbg * 4 + fb;
    const int fjl0 = fjg * 2;

    // xp prefetch for t = 0
    float2 xv[3];
    if (tid < 128) {
        const size_t row = ((size_t)(b0 + fbl) * T_SZ + 0) * G3_SZ;
#pragma unroll
        for (int g = 0; g < 3; g++)
            xv[g] = *(const float2*)(xp + row + g * H_SZ + j0 + fjl0);
    }

    for (int t = 0; t < T_SZ; t++) {
        // ---- warp-local h staging (delta (i): no block-wide stage sync)
        if (t == 0) {
            const float4 z = make_float4(0.f, 0.f, 0.f, 0.f);
#pragma unroll
            for (int u = 0; u < 4; u++)
                *(float4*)&s.hs[st_row + 4 * u][st_col] = z;
        } else {
            float4 v[4];
#pragma unroll
            for (int u = 0; u < 4; u++)
                v[u] = *(const float4*)(hseq +
                        ((size_t)(b0 + st_row + 4 * u) * T_SZ + (t - 1)) * H_SZ + st_col);
#pragma unroll
            for (int u = 0; u < 4; u++)
                *(float4*)&s.hs[st_row + 4 * u][st_col] = v[u];
        }
        __syncwarp();

        // ---- partial dots: 4b x 2j x 3g over this warp's 32 k's
        u64 acc[4][3];
#pragma unroll
        for (int b = 0; b < 4; b++)
#pragma unroll
            for (int g = 0; g < 3; g++) acc[b][g] = 0ull;

        {
            const float* wr = &s.ws[0][jg][ks * 64];
            const float* wz = &s.ws[1][jg][ks * 64];
            const float* wn = &s.ws[2][jg][ks * 64];
            const float* hb = &s.hs[bg * 4][ks * 32];
#pragma unroll 2
            for (int c = 0; c < 8; c++) {
                ulonglong2 rA = *(const ulonglong2*)(wr + c * 8);
                ulonglong2 rB = *(const ulonglong2*)(wr + c * 8 + 4);
                ulonglong2 zA = *(const ulonglong2*)(wz + c * 8);
                ulonglong2 zB = *(const ulonglong2*)(wz + c * 8 + 4);
                ulonglong2 nA = *(const ulonglong2*)(wn + c * 8);
                ulonglong2 nB = *(const ulonglong2*)(wn + c * 8 + 4);
#pragma unroll
                for (int b = 0; b < 4; b++) {
                    float4 h = *(const float4*)(hb + b * 516 + c * 4);
                    u64 a0 = splat2(h.x), a1 = splat2(h.y);
                    u64 a2 = splat2(h.z), a3 = splat2(h.w);
                    fma2(acc[b][0], a0, rA.x); fma2(acc[b][0], a1, rA.y);
                    fma2(acc[b][0], a2, rB.x); fma2(acc[b][0], a3, rB.y);
                    fma2(acc[b][1], a0, zA.x); fma2(acc[b][1], a1, zA.y);
                    fma2(acc[b][1], a2, zB.x); fma2(acc[b][1], a3, zB.y);
                    fma2(acc[b][2], a0, nA.x); fma2(acc[b][2], a1, nA.y);
                    fma2(acc[b][2], a2, nB.x); fma2(acc[b][2], a3, nB.y);
                }
            }
        }

        // ---- write partials: [b][g][p] order, 12 x STS.64
        {
            float* rp = &s.red[tid][0];
#pragma unroll
            for (int b = 0; b < 4; b++)
#pragma unroll
                for (int g = 0; g < 3; g++)
                    *(float2*)(rp + b * 6 + g * 2) = unpack2(acc[b][g]);
        }
        __syncthreads();

        // ---- finalize: tid < 128, each 1 batch x 2 j; sum 16 k-slices
        if (tid < 128) {
            float2 t0 = make_float2(0.f, 0.f), t1 = t0, t2 = t0;
#pragma unroll
            for (int sdx = 0; sdx < 16; sdx++) {
                const float* rp = &s.red[sdx * 32 + fi5][fb * 6];
                float2 a = *(const float2*)(rp + 0);
                float2 b = *(const float2*)(rp + 2);
                float2 c = *(const float2*)(rp + 4);
                t0.x += a.x; t0.y += a.y;
                t1.x += b.x; t1.y += b.y;
                t2.x += c.x; t2.y += c.y;
            }
            float2 hv;
#pragma unroll
            for (int p = 0; p < 2; p++) {
                const int jl = fjl0 + p;
                float dr = (p == 0) ? t0.x : t0.y;
                float dz = (p == 0) ? t1.x : t1.y;
                float dn = (p == 0) ? t2.x : t2.y;
                float xr = (p == 0) ? xv[0].x : xv[0].y;
                float xz = (p == 0) ? xv[1].x : xv[1].y;
                float xn = (p == 0) ? xv[2].x : xv[2].y;
                float rg = 1.f / (1.f + __expf(-(xr + dr + s.bhs[jl])));
                float zg = 1.f / (1.f + __expf(-(xz + dz + s.bhs[16 + jl])));
                float ng = tanhf(xn + rg * (dn + s.bhs[32 + jl]));
                float hp = s.hs[fbl][j0 + jl];
                float h  = (1.f - zg) * ng + zg * hp;
                if (p == 0) hv.x = h; else hv.y = h;
            }
            *(float2*)(hseq + ((size_t)(b0 + fbl) * T_SZ + t) * H_SZ + j0 + fjl0) = hv;

            // prefetch xp for next step (overlaps the barrier)
            const int tn = (t + 1 < T_SZ) ? t + 1 : t;
            const size_t row = ((size_t)(b0 + fbl) * T_SZ + tn) * G3_SZ;
#pragma unroll
            for (int g = 0; g < 3; g++)
                xv[g] = *(const float2*)(xp + row + g * H_SZ + j0 + fjl0);
        }
        __syncthreads();   // finalize STGs + hs reads complete block-wide

        // ---- two-hop group barrier; skipped uniformly on the last step (ii)
        if (t + 1 < T_SZ) {
            const unsigned tgt = base_flag + (unsigned)t + 1u;
            if (tid == 0) st_rel(&g_flags[bt][jt], tgt);
            if (jt == 0) {
                if (tid < 32) {
                    while ((int)(ld_acq(&g_flags[bt][lane]) - tgt) < 0) { }
                    __syncwarp();
                    if (tid == 0) st_rel(&g_genf[bt][0], base_gen + (unsigned)t + 1u);
                }
            } else if (tid == 0) {
                const unsigned gt = base_gen + (unsigned)t + 1u;
                while ((int)(ld_acq(&g_genf[bt][0]) - gt) < 0) { }
            }
            __syncthreads();
        }
    }
}

// ---------------------------------------------------------------------------
// Launch
// ---------------------------------------------------------------------------
extern "C" void kernel_launch(void* const* d_in, const int* in_sizes, int n_in,
                              void* d_out, int out_size)
{
    (void)in_sizes; (void)n_in; (void)out_size;
    const float* x    = (const float*)d_in[0];
    const float* Wih0 = (const float*)d_in[1];
    const float* Whh0 = (const float*)d_in[2];
    const float* bih0 = (const float*)d_in[3];
    const float* bhh0 = (const float*)d_in[4];
    const float* Wih1 = (const float*)d_in[5];
    const float* Whh1 = (const float*)d_in[6];
    const float* bih1 = (const float*)d_in[7];
    const float* bhh1 = (const float*)d_in[8];
    const float* Wih2 = (const float*)d_in[9];
    const float* Whh2 = (const float*)d_in[10];
    const float* bih2 = (const float*)d_in[11];
    const float* bhh2 = (const float*)d_in[12];
    const float* Wout = (const float*)d_in[13];
    const float* bout = (const float*)d_in[14];
    float* out = (float*)d_out;

    cudaFuncSetAttribute(scan_kernel, cudaFuncAttributeMaxDynamicSharedMemorySize,
                         (int)sizeof(ScanSmem));

    void *xp_v = nullptr, *hs_v = nullptr;
    cudaGetSymbolAddress(&xp_v, g_xp);
    cudaGetSymbolAddress(&hs_v, g_hseq);
    float* xpd = (float*)xp_v;
    float* hs  = (float*)hs_v;

    const dim3 gblk(256), sblk(512);
    const dim3 g_proj(G3_SZ / 128, M_SZ / 128);
    const dim3 g_head(O_SZ / 128,  M_SZ / 128);
    const size_t scan_smem = sizeof(ScanSmem);

    gemm_bias_kernel<<<g_proj, gblk>>>(x,  Wih0, bih0, xpd, M_SZ, G3_SZ, F_SZ);
    scan_kernel<<<SCAN_NBLK, sblk, scan_smem>>>(Whh0, bhh0, xpd, hs);
    gemm_bias_kernel<<<g_proj, gblk>>>(hs, Wih1, bih1, xpd, M_SZ, G3_SZ, H_SZ);
    scan_kernel<<<SCAN_NBLK, sblk, scan_smem>>>(Whh1, bhh1, xpd, hs);
    gemm_bias_kernel<<<g_proj, gblk>>>(hs, Wih2, bih2, xpd, M_SZ, G3_SZ, H_SZ);
    scan_kernel<<<SCAN_NBLK, sblk, scan_smem>>>(Whh2, bhh2, xpd, hs);
    gemm_bias_kernel<<<g_head, gblk>>>(hs, Wout, bout, out, M_SZ, O_SZ, H_SZ);
}

// round 12
// speedup vs baseline: 2.0608x; 1.1602x over previous
#include <cuda_runtime.h>
#include <cuda_bf16.h>
#include <cstdint>

// ---------------------------------------------------------------------------
// 3-layer GRU + linear head. B=64, T=512, F=128, H=512, 3H=1536, O=128.
// Scan: R5-exact persistent fp32 kernel (best-known config).
// GEMMs: mma.sync m16n8k16 bf16 split-precision (hi/lo, 3 products) --
// the only tensor path that compiles for the harness's compute_103 target.
// ---------------------------------------------------------------------------
#define B_SZ   64
#define T_SZ   512
#define F_SZ   128
#define H_SZ   512
#define G3_SZ  1536
#define O_SZ   128
#define M_SZ   (B_SZ * T_SZ)

#define SCAN_NBLK  128

typedef unsigned long long u64;
typedef unsigned int u32;

__device__ __forceinline__ u64 splat2(float x) {
    u64 r; asm("mov.b64 %0, {%1, %1};" : "=l"(r) : "f"(x)); return r;
}
__device__ __forceinline__ void fma2(u64 &d, u64 a, u64 b) {
    asm("fma.rn.f32x2 %0, %1, %2, %0;" : "+l"(d) : "l"(a), "l"(b));
}
__device__ __forceinline__ float2 unpack2(u64 v) {
    float2 f; asm("mov.b64 {%0, %1}, %2;" : "=f"(f.x), "=f"(f.y) : "l"(v)); return f;
}
__device__ __forceinline__ unsigned ld_acq(const unsigned* p) {
    unsigned v; asm volatile("ld.global.acquire.gpu.u32 %0, [%1];" : "=r"(v) : "l"(p) : "memory"); return v;
}
__device__ __forceinline__ void st_rel(unsigned* p, unsigned v) {
    asm volatile("st.global.release.gpu.u32 [%0], %1;" :: "l"(p), "r"(v) : "memory");
}

// ---------------------------------------------------------------------------
// Scratch (device globals -- allocation-free per harness rules)
// ---------------------------------------------------------------------------
__device__ float    g_xp[(size_t)M_SZ * G3_SZ];
__device__ float    g_hseq[(size_t)M_SZ * H_SZ];
__device__ unsigned g_flags[4][32];
__device__ unsigned g_genf[4][32];

// ===========================================================================
// bf16 split-precision tensor GEMM: C[M,N] = A[M,K] @ W[N,K]^T + bias[N].
// Block 256 thr = 8 warps; tile 128x128, BK=32. Warp = 64(M) x 32(N):
// 4 m-tiles x 4 n-tiles of m16n8k16. 3 products (Ahi*Whi + Ahi*Wlo + Alo*Whi)
// accumulate in fp32 -> rel err ~2^-16 per product, ~1e-5 on the dot.
// Smem pitch 40 bf16 (80B = 20 banks): fragment LDS hits all 32 banks once.
// ===========================================================================
#define AP 40   // smem pitch in bf16 elements

__device__ __forceinline__ void mma_bf16(float* d, const u32* a, const u32* b) {
    asm volatile(
        "mma.sync.aligned.m16n8k16.row.col.f32.bf16.bf16.f32 "
        "{%0,%1,%2,%3}, {%4,%5,%6,%7}, {%8,%9}, {%0,%1,%2,%3};"
        : "+f"(d[0]), "+f"(d[1]), "+f"(d[2]), "+f"(d[3])
        : "r"(a[0]), "r"(a[1]), "r"(a[2]), "r"(a[3]), "r"(b[0]), "r"(b[1]));
}

__device__ __forceinline__ u32 pack_bf2(__nv_bfloat16 lo16, __nv_bfloat16 hi16) {
    __nv_bfloat162 t; t.x = lo16; t.y = hi16;   // .x = low half
    return *(u32*)&t;
}

// split one float into bf16 hi + bf16 lo (residual)
__device__ __forceinline__ void split_bf(float x, __nv_bfloat16& h, __nv_bfloat16& l) {
    h = __float2bfloat16_rn(x);
    l = __float2bfloat16_rn(x - __bfloat162float(h));
}

__global__ void __launch_bounds__(256)
tgemm_kernel(const float* __restrict__ A, const float* __restrict__ W,
             const float* __restrict__ bias, float* __restrict__ C,
             int M, int N, int K)
{
    __shared__ __align__(16) unsigned short Ahi[128 * AP];
    __shared__ __align__(16) unsigned short Alo[128 * AP];
    __shared__ __align__(16) unsigned short Whi[128 * AP];
    __shared__ __align__(16) unsigned short Wlo[128 * AP];

    const int tid  = threadIdx.x;
    const int wid  = tid >> 5;
    const int lane = tid & 31;
    const int n0   = blockIdx.x * 128;
    const int m0   = blockIdx.y * 128;

    const int wm = wid & 1;        // 0..1 : 64 M-rows each
    const int wn = wid >> 1;       // 0..3 : 32 N-cols each

    const int qrow = lane >> 2;    // 0..7
    const int qk   = lane & 3;     // 0..3

    float acc[4][4][4];
#pragma unroll
    for (int i = 0; i < 4; i++)
#pragma unroll
        for (int j = 0; j < 4; j++)
#pragma unroll
            for (int c = 0; c < 4; c++) acc[i][j][c] = 0.f;

    const int srow = tid >> 1;          // staging row 0..127
    const int scol = (tid & 1) * 16;    // 0 or 16

    const int nchunk = K >> 5;
    for (int kc = 0; kc < nchunk; kc++) {
        // ---- stage: load fp32 chunk, split to bf16 hi/lo, store to smem
#pragma unroll
        for (int q = 0; q < 4; q++) {
            const int col = scol + q * 4;
            float4 av = *(const float4*)(A + (size_t)(m0 + srow) * K + kc * 32 + col);
            __nv_bfloat16 h0, l0, h1, l1, h2, l2, h3, l3;
            split_bf(av.x, h0, l0); split_bf(av.y, h1, l1);
            split_bf(av.z, h2, l2); split_bf(av.w, h3, l3);
            *(u32*)&Ahi[srow * AP + col]     = pack_bf2(h0, h1);
            *(u32*)&Ahi[srow * AP + col + 2] = pack_bf2(h2, h3);
            *(u32*)&Alo[srow * AP + col]     = pack_bf2(l0, l1);
            *(u32*)&Alo[srow * AP + col + 2] = pack_bf2(l2, l3);

            float4 wv = *(const float4*)(W + (size_t)(n0 + srow) * K + kc * 32 + col);
            split_bf(wv.x, h0, l0); split_bf(wv.y, h1, l1);
            split_bf(wv.z, h2, l2); split_bf(wv.w, h3, l3);
            *(u32*)&Whi[srow * AP + col]     = pack_bf2(h0, h1);
            *(u32*)&Whi[srow * AP + col + 2] = pack_bf2(h2, h3);
            *(u32*)&Wlo[srow * AP + col]     = pack_bf2(l0, l1);
            *(u32*)&Wlo[srow * AP + col + 2] = pack_bf2(l2, l3);
        }
        __syncthreads();

        // ---- two k16 steps per chunk
#pragma unroll
        for (int ks = 0; ks < 2; ks++) {
            const int k16 = ks * 16;
            u32 afh[4][4], afl[4][4];   // A fragments hi/lo, 4 m-tiles
            u32 bfh[4][2], bfl[4][2];   // B fragments hi/lo, 4 n-tiles
#pragma unroll
            for (int mt = 0; mt < 4; mt++) {
                const int r0 = (wm * 64 + mt * 16 + qrow) * AP + k16 + qk * 2;
                afh[mt][0] = *(const u32*)&Ahi[r0];
                afh[mt][1] = *(const u32*)&Ahi[r0 + 8 * AP];
                afh[mt][2] = *(const u32*)&Ahi[r0 + 8];
                afh[mt][3] = *(const u32*)&Ahi[r0 + 8 * AP + 8];
                afl[mt][0] = *(const u32*)&Alo[r0];
                afl[mt][1] = *(const u32*)&Alo[r0 + 8 * AP];
                afl[mt][2] = *(const u32*)&Alo[r0 + 8];
                afl[mt][3] = *(const u32*)&Alo[r0 + 8 * AP + 8];
            }
#pragma unroll
            for (int nt = 0; nt < 4; nt++) {
                const int r0 = (wn * 32 + nt * 8 + qrow) * AP + k16 + qk * 2;
                bfh[nt][0] = *(const u32*)&Whi[r0];
                bfh[nt][1] = *(const u32*)&Whi[r0 + 8];
                bfl[nt][0] = *(const u32*)&Wlo[r0];
                bfl[nt][1] = *(const u32*)&Wlo[r0 + 8];
            }
#pragma unroll
            for (int mt = 0; mt < 4; mt++)
#pragma unroll
                for (int nt = 0; nt < 4; nt++) {
                    mma_bf16(acc[mt][nt], afh[mt], bfh[nt]);
                    mma_bf16(acc[mt][nt], afh[mt], bfl[nt]);
                    mma_bf16(acc[mt][nt], afl[mt], bfh[nt]);
                }
        }
        __syncthreads();
    }

    // ---- epilogue: D fragment c0,c1 -> (row, col..col+1); c2,c3 -> row+8
#pragma unroll
    for (int mt = 0; mt < 4; mt++) {
        const int mrow = m0 + wm * 64 + mt * 16 + qrow;
#pragma unroll
        for (int nt = 0; nt < 4; nt++) {
            const int ncol = n0 + wn * 32 + nt * 8 + qk * 2;
            const float b0 = bias[ncol], b1 = bias[ncol + 1];
            float2 v0 = make_float2(acc[mt][nt][0] + b0, acc[mt][nt][1] + b1);
            float2 v1 = make_float2(acc[mt][nt][2] + b0, acc[mt][nt][3] + b1);
            *(float2*)(C + (size_t)mrow * N + ncol)       = v0;
            *(float2*)(C + (size_t)(mrow + 8) * N + ncol) = v1;
        }
    }
}

// ---------------------------------------------------------------------------
// Persistent GRU scan (R5 exact). 128 blocks = 4 batch-groups x 32 j-tiles,
// 512 threads. jg = tid&7, bg = (tid>>3)&3, ks = tid>>5 (k-split 16).
// Micro-tile 4b x 2j x 3g packed f32x2; Whh SMEM-resident all 512 steps.
// Barrier: two-hop (leader warp polls 32 flags; others spin one gen word).
// ---------------------------------------------------------------------------
struct ScanSmem {
    float    ws[3][8][1028];
    float    hs[16][516];
    float    red[512][26];
    float    bhs[48];
    unsigned baseu[2];
};

__global__ void __launch_bounds__(512, 1)
scan_kernel(const float* __restrict__ Whh, const float* __restrict__ bhh,
            const float* __restrict__ xp, float* __restrict__ hseq)
{
    extern __shared__ ScanSmem smem[];
    ScanSmem& s = smem[0];

    const int tid = threadIdx.x;
    const int jg  = tid & 7;
    const int bg  = (tid >> 3) & 3;
    const int ks  = tid >> 5;
    const int bt  = blockIdx.x >> 5;
    const int jt  = blockIdx.x & 31;
    const int b0  = bt * 16;
    const int j0  = jt * 16;

    if (tid == 0) {
        s.baseu[0] = ld_acq(&g_flags[bt][jt]);
        s.baseu[1] = ld_acq(&g_genf[bt][0]);
    }

    for (int i = tid; i < 48 * 128; i += 512) {
        const int rl = i >> 7, k4 = i & 127;
        const int gg = rl >> 4, jj = rl & 15;
        float4 v = *(const float4*)(Whh + (size_t)(gg * H_SZ + j0 + jj) * H_SZ + k4 * 4);
        const int jp = jj >> 1, p = jj & 1;
        float* w = &s.ws[gg][jp][0];
        w[(k4 * 4 + 0) * 2 + p] = v.x;
        w[(k4 * 4 + 1) * 2 + p] = v.y;
        w[(k4 * 4 + 2) * 2 + p] = v.z;
        w[(k4 * 4 + 3) * 2 + p] = v.w;
    }
    if (tid < 48) s.bhs[tid] = bhh[(tid >> 4) * H_SZ + j0 + (tid & 15)];
    __syncthreads();

    const unsigned base_flag = s.baseu[0];
    const unsigned base_gen  = s.baseu[1];

    const int fb   = tid >> 5;
    const int fi5  = tid & 31;
    const int fbg  = fi5 >> 3;
    const int fjg  = fi5 & 7;
    const int fbl  = fbg * 4 + fb;
    const int fjl0 = fjg * 2;

    float2 xv[3];
    if (tid < 128) {
        const size_t row = ((size_t)(b0 + fbl) * T_SZ + 0) * G3_SZ;
#pragma unroll
        for (int g = 0; g < 3; g++)
            xv[g] = *(const float2*)(xp + row + g * H_SZ + j0 + fjl0);
    }

    for (int t = 0; t < T_SZ; t++) {
        if (t == 0) {
            float4 z = make_float4(0.f, 0.f, 0.f, 0.f);
            for (int i = tid; i < 16 * 129; i += 512)
                ((float4*)&s.hs[0][0])[i] = z;
        } else {
#pragma unroll
            for (int u = 0; u < 4; u++) {
                const int i = tid + u * 512;
                const int b = i >> 7, k4 = i & 127;
                float4 v = *(const float4*)(hseq + ((size_t)(b0 + b) * T_SZ + (t - 1)) * H_SZ + k4 * 4);
                *(float4*)&s.hs[b][k4 * 4] = v;
            }
        }
        __syncthreads();

        u64 acc[4][3];
#pragma unroll
        for (int b = 0; b < 4; b++)
#pragma unroll
            for (int g = 0; g < 3; g++) acc[b][g] = 0ull;

        {
            const float* wr = &s.ws[0][jg][ks * 64];
            const float* wz = &s.ws[1][jg][ks * 64];
            const float* wn = &s.ws[2][jg][ks * 64];
            const float* hb = &s.hs[bg * 4][ks * 32];
#pragma unroll 2
            for (int c = 0; c < 8; c++) {
                ulonglong2 rA = *(const ulonglong2*)(wr + c * 8);
                ulonglong2 rB = *(const ulonglong2*)(wr + c * 8 + 4);
                ulonglong2 zA = *(const ulonglong2*)(wz + c * 8);
                ulonglong2 zB = *(const ulonglong2*)(wz + c * 8 + 4);
                ulonglong2 nA = *(const ulonglong2*)(wn + c * 8);
                ulonglong2 nB = *(const ulonglong2*)(wn + c * 8 + 4);
#pragma unroll
                for (int b = 0; b < 4; b++) {
                    float4 h = *(const float4*)(hb + b * 516 + c * 4);
                    u64 a0 = splat2(h.x), a1 = splat2(h.y);
                    u64 a2 = splat2(h.z), a3 = splat2(h.w);
                    fma2(acc[b][0], a0, rA.x); fma2(acc[b][0], a1, rA.y);
                    fma2(acc[b][0], a2, rB.x); fma2(acc[b][0], a3, rB.y);
                    fma2(acc[b][1], a0, zA.x); fma2(acc[b][1], a1, zA.y);
                    fma2(acc[b][1], a2, zB.x); fma2(acc[b][1], a3, zB.y);
                    fma2(acc[b][2], a0, nA.x); fma2(acc[b][2], a1, nA.y);
                    fma2(acc[b][2], a2, nB.x); fma2(acc[b][2], a3, nB.y);
                }
            }
        }

        {
            float* rp = &s.red[tid][0];
#pragma unroll
            for (int b = 0; b < 4; b++)
#pragma unroll
                for (int g = 0; g < 3; g++)
                    *(float2*)(rp + b * 6 + g * 2) = unpack2(acc[b][g]);
        }
        __syncthreads();

        if (tid < 128) {
            float2 t0 = make_float2(0.f, 0.f), t1 = t0, t2 = t0;
#pragma unroll
            for (int sdx = 0; sdx < 16; sdx++) {
                const float* rp = &s.red[sdx * 32 + fi5][fb * 6];
                float2 a = *(const float2*)(rp + 0);
                float2 b = *(const float2*)(rp + 2);
                float2 c = *(const float2*)(rp + 4);
                t0.x += a.x; t0.y += a.y;
                t1.x += b.x; t1.y += b.y;
                t2.x += c.x; t2.y += c.y;
            }
            float2 hv;
#pragma unroll
            for (int p = 0; p < 2; p++) {
                const int jl = fjl0 + p;
                float dr = (p == 0) ? t0.x : t0.y;
                float dz = (p == 0) ? t1.x : t1.y;
                float dn = (p == 0) ? t2.x : t2.y;
                float xr = (p == 0) ? xv[0].x : xv[0].y;
                float xz = (p == 0) ? xv[1].x : xv[1].y;
                float xn = (p == 0) ? xv[2].x : xv[2].y;
                float rg = 1.f / (1.f + __expf(-(xr + dr + s.bhs[jl])));
                float zg = 1.f / (1.f + __expf(-(xz + dz + s.bhs[16 + jl])));
                float ng = tanhf(xn + rg * (dn + s.bhs[32 + jl]));
                float hp = s.hs[fbl][j0 + jl];
                float h  = (1.f - zg) * ng + zg * hp;
                if (p == 0) hv.x = h; else hv.y = h;
            }
            *(float2*)(hseq + ((size_t)(b0 + fbl) * T_SZ + t) * H_SZ + j0 + fjl0) = hv;

            const int tn = (t + 1 < T_SZ) ? t + 1 : t;
            const size_t row = ((size_t)(b0 + fbl) * T_SZ + tn) * G3_SZ;
#pragma unroll
            for (int g = 0; g < 3; g++)
                xv[g] = *(const float2*)(xp + row + g * H_SZ + j0 + fjl0);
        }
        __syncthreads();

        {
            const unsigned tgt = base_flag + (unsigned)t + 1u;
            if (tid == 0) st_rel(&g_flags[bt][jt], tgt);
            if (jt == 0) {
                if (tid < 32) {
                    while ((int)(ld_acq(&g_flags[bt][tid]) - tgt) < 0) { }
                    __syncwarp();
                    if (tid == 0) st_rel(&g_genf[bt][0], base_gen + (unsigned)t + 1u);
                }
            } else if (tid == 0) {
                const unsigned gt = base_gen + (unsigned)t + 1u;
                while ((int)(ld_acq(&g_genf[bt][0]) - gt) < 0) { }
            }
        }
        __syncthreads();
    }
}

// ---------------------------------------------------------------------------
// Launch
// ---------------------------------------------------------------------------
extern "C" void kernel_launch(void* const* d_in, const int* in_sizes, int n_in,
                              void* d_out, int out_size)
{
    (void)in_sizes; (void)n_in; (void)out_size;
    const float* x    = (const float*)d_in[0];
    const float* Wih0 = (const float*)d_in[1];
    const float* Whh0 = (const float*)d_in[2];
    const float* bih0 = (const float*)d_in[3];
    const float* bhh0 = (const float*)d_in[4];
    const float* Wih1 = (const float*)d_in[5];
    const float* Whh1 = (const float*)d_in[6];
    const float* bih1 = (const float*)d_in[7];
    const float* bhh1 = (const float*)d_in[8];
    const float* Wih2 = (const float*)d_in[9];
    const float* Whh2 = (const float*)d_in[10];
    const float* bih2 = (const float*)d_in[11];
    const float* bhh2 = (const float*)d_in[12];
    const float* Wout = (const float*)d_in[13];
    const float* bout = (const float*)d_in[14];
    float* out = (float*)d_out;

    cudaFuncSetAttribute(scan_kernel, cudaFuncAttributeMaxDynamicSharedMemorySize,
                         (int)sizeof(ScanSmem));

    void *xp_v = nullptr, *hs_v = nullptr;
    cudaGetSymbolAddress(&xp_v, g_xp);
    cudaGetSymbolAddress(&hs_v, g_hseq);
    float* xpd = (float*)xp_v;
    float* hs  = (float*)hs_v;

    const dim3 tblk(256), sblk(512);
    const dim3 g_proj(G3_SZ / 128, M_SZ / 128);   // 12 x 256
    const dim3 g_head(O_SZ / 128,  M_SZ / 128);   // 1 x 256
    const size_t scan_smem = sizeof(ScanSmem);

    tgemm_kernel<<<g_proj, tblk>>>(x,  Wih0, bih0, xpd, M_SZ, G3_SZ, F_SZ);
    scan_kernel<<<SCAN_NBLK, sblk, scan_smem>>>(Whh0, bhh0, xpd, hs);
    tgemm_kernel<<<g_proj, tblk>>>(hs, Wih1, bih1, xpd, M_SZ, G3_SZ, H_SZ);
    scan_kernel<<<SCAN_NBLK, sblk, scan_smem>>>(Whh1, bhh1, xpd, hs);
    tgemm_kernel<<<g_proj, tblk>>>(hs, Wih2, bih2, xpd, M_SZ, G3_SZ, H_SZ);
    scan_kernel<<<SCAN_NBLK, sblk, scan_smem>>>(Whh2, bhh2, xpd, hs);
    tgemm_kernel<<<g_head, tblk>>>(hs, Wout, bout, out, M_SZ, O_SZ, H_SZ);
}

// round 13
// speedup vs baseline: 2.5884x; 1.2560x over previous
#include <cuda_runtime.h>
#include <cuda_bf16.h>
#include <cstdint>

// ---------------------------------------------------------------------------
// 3-layer GRU + linear head. B=64, T=512, F=128, H=512, 3H=1536, O=128.
// GEMMs: R12 bf16 split-precision mma (validated). Scan: NEW -- same mma
// path for the recurrent matvec; fp32 state carried in finalizer registers.
// ---------------------------------------------------------------------------
#define B_SZ   64
#define T_SZ   512
#define F_SZ   128
#define H_SZ   512
#define G3_SZ  1536
#define O_SZ   128
#define M_SZ   (B_SZ * T_SZ)

#define SCAN_NBLK  128

typedef unsigned long long u64;
typedef unsigned int u32;

__device__ __forceinline__ u64 splat2(float x) {
    u64 r; asm("mov.b64 %0, {%1, %1};" : "=l"(r) : "f"(x)); return r;
}
__device__ __forceinline__ void fma2(u64 &d, u64 a, u64 b) {
    asm("fma.rn.f32x2 %0, %1, %2, %0;" : "+l"(d) : "l"(a), "l"(b));
}
__device__ __forceinline__ float2 unpack2(u64 v) {
    float2 f; asm("mov.b64 {%0, %1}, %2;" : "=f"(f.x), "=f"(f.y) : "l"(v)); return f;
}
__device__ __forceinline__ unsigned ld_acq(const unsigned* p) {
    unsigned v; asm volatile("ld.global.acquire.gpu.u32 %0, [%1];" : "=r"(v) : "l"(p) : "memory"); return v;
}
__device__ __forceinline__ void st_rel(unsigned* p, unsigned v) {
    asm volatile("st.global.release.gpu.u32 [%0], %1;" :: "l"(p), "r"(v) : "memory");
}

// ---------------------------------------------------------------------------
// Scratch (device globals -- allocation-free per harness rules)
// ---------------------------------------------------------------------------
__device__ float    g_xp[(size_t)M_SZ * G3_SZ];
__device__ float    g_hseq[(size_t)M_SZ * H_SZ];
__device__ u32      g_hbf[4][T_SZ][8192];     // frag-ordered bf16 hi/lo h
__device__ unsigned g_flags[4][32];
__device__ unsigned g_genf[4][32];

// ===========================================================================
// Shared mma helpers (conventions validated in R12)
// ===========================================================================
__device__ __forceinline__ void mma_bf16(float* d, const u32* a, const u32* b) {
    asm volatile(
        "mma.sync.aligned.m16n8k16.row.col.f32.bf16.bf16.f32 "
        "{%0,%1,%2,%3}, {%4,%5,%6,%7}, {%8,%9}, {%0,%1,%2,%3};"
        : "+f"(d[0]), "+f"(d[1]), "+f"(d[2]), "+f"(d[3])
        : "r"(a[0]), "r"(a[1]), "r"(a[2]), "r"(a[3]), "r"(b[0]), "r"(b[1]));
}
__device__ __forceinline__ u32 pack_bf2(__nv_bfloat16 lo16, __nv_bfloat16 hi16) {
    __nv_bfloat162 t; t.x = lo16; t.y = hi16;   // .x = low half = first k
    return *(u32*)&t;
}
__device__ __forceinline__ void split_bf(float x, __nv_bfloat16& h, __nv_bfloat16& l) {
    h = __float2bfloat16_rn(x);
    l = __float2bfloat16_rn(x - __bfloat162float(h));
}

// ===========================================================================
// bf16 split-precision tensor GEMM (R12 exact).
// ===========================================================================
#define AP 40

__global__ void __launch_bounds__(256)
tgemm_kernel(const float* __restrict__ A, const float* __restrict__ W,
             const float* __restrict__ bias, float* __restrict__ C,
             int M, int N, int K)
{
    __shared__ __align__(16) unsigned short Ahi[128 * AP];
    __shared__ __align__(16) unsigned short Alo[128 * AP];
    __shared__ __align__(16) unsigned short Whi[128 * AP];
    __shared__ __align__(16) unsigned short Wlo[128 * AP];

    const int tid  = threadIdx.x;
    const int wid  = tid >> 5;
    const int lane = tid & 31;
    const int n0   = blockIdx.x * 128;
    const int m0   = blockIdx.y * 128;

    const int wm = wid & 1;
    const int wn = wid >> 1;
    const int qrow = lane >> 2;
    const int qk   = lane & 3;

    float acc[4][4][4];
#pragma unroll
    for (int i = 0; i < 4; i++)
#pragma unroll
        for (int j = 0; j < 4; j++)
#pragma unroll
            for (int c = 0; c < 4; c++) acc[i][j][c] = 0.f;

    const int srow = tid >> 1;
    const int scol = (tid & 1) * 16;

    const int nchunk = K >> 5;
    for (int kc = 0; kc < nchunk; kc++) {
#pragma unroll
        for (int q = 0; q < 4; q++) {
            const int col = scol + q * 4;
            float4 av = *(const float4*)(A + (size_t)(m0 + srow) * K + kc * 32 + col);
            __nv_bfloat16 h0, l0, h1, l1, h2, l2, h3, l3;
            split_bf(av.x, h0, l0); split_bf(av.y, h1, l1);
            split_bf(av.z, h2, l2); split_bf(av.w, h3, l3);
            *(u32*)&Ahi[srow * AP + col]     = pack_bf2(h0, h1);
            *(u32*)&Ahi[srow * AP + col + 2] = pack_bf2(h2, h3);
            *(u32*)&Alo[srow * AP + col]     = pack_bf2(l0, l1);
            *(u32*)&Alo[srow * AP + col + 2] = pack_bf2(l2, l3);

            float4 wv = *(const float4*)(W + (size_t)(n0 + srow) * K + kc * 32 + col);
            split_bf(wv.x, h0, l0); split_bf(wv.y, h1, l1);
            split_bf(wv.z, h2, l2); split_bf(wv.w, h3, l3);
            *(u32*)&Whi[srow * AP + col]     = pack_bf2(h0, h1);
            *(u32*)&Whi[srow * AP + col + 2] = pack_bf2(h2, h3);
            *(u32*)&Wlo[srow * AP + col]     = pack_bf2(l0, l1);
            *(u32*)&Wlo[srow * AP + col + 2] = pack_bf2(l2, l3);
        }
        __syncthreads();

#pragma unroll
        for (int ks = 0; ks < 2; ks++) {
            const int k16 = ks * 16;
            u32 afh[4][4], afl[4][4];
            u32 bfh[4][2], bfl[4][2];
#pragma unroll
            for (int mt = 0; mt < 4; mt++) {
                const int r0 = (wm * 64 + mt * 16 + qrow) * AP + k16 + qk * 2;
                afh[mt][0] = *(const u32*)&Ahi[r0];
                afh[mt][1] = *(const u32*)&Ahi[r0 + 8 * AP];
                afh[mt][2] = *(const u32*)&Ahi[r0 + 8];
                afh[mt][3] = *(const u32*)&Ahi[r0 + 8 * AP + 8];
                afl[mt][0] = *(const u32*)&Alo[r0];
                afl[mt][1] = *(const u32*)&Alo[r0 + 8 * AP];
                afl[mt][2] = *(const u32*)&Alo[r0 + 8];
                afl[mt][3] = *(const u32*)&Alo[r0 + 8 * AP + 8];
            }
#pragma unroll
            for (int nt = 0; nt < 4; nt++) {
                const int r0 = (wn * 32 + nt * 8 + qrow) * AP + k16 + qk * 2;
                bfh[nt][0] = *(const u32*)&Whi[r0];
                bfh[nt][1] = *(const u32*)&Whi[r0 + 8];
                bfl[nt][0] = *(const u32*)&Wlo[r0];
                bfl[nt][1] = *(const u32*)&Wlo[r0 + 8];
            }
#pragma unroll
            for (int mt = 0; mt < 4; mt++)
#pragma unroll
                for (int nt = 0; nt < 4; nt++) {
                    mma_bf16(acc[mt][nt], afh[mt], bfh[nt]);
                    mma_bf16(acc[mt][nt], afh[mt], bfl[nt]);
                    mma_bf16(acc[mt][nt], afl[mt], bfh[nt]);
                }
        }
        __syncthreads();
    }

#pragma unroll
    for (int mt = 0; mt < 4; mt++) {
        const int mrow = m0 + wm * 64 + mt * 16 + qrow;
#pragma unroll
        for (int nt = 0; nt < 4; nt++) {
            const int ncol = n0 + wn * 32 + nt * 8 + qk * 2;
            const float b0 = bias[ncol], b1 = bias[ncol + 1];
            float2 v0 = make_float2(acc[mt][nt][0] + b0, acc[mt][nt][1] + b1);
            float2 v1 = make_float2(acc[mt][nt][2] + b0, acc[mt][nt][3] + b1);
            *(float2*)(C + (size_t)mrow * N + ncol)       = v0;
            *(float2*)(C + (size_t)(mrow + 8) * N + ncol) = v1;
        }
    }
}

// ===========================================================================
// Persistent GRU scan with tensor-core dot.
// 128 blocks = 4 batch-groups x 32 j-tiles, 512 threads = 16 warps.
// Warp ks handles k-chunks {2ks, 2ks+1} (k16 each): 6 n-tiles x 3 products
// x 2 chunks = 36 mma. Weights pre-built as B-fragments (bf16 hi/lo) in smem.
// h flows as pre-built A-fragments: finalizers write packed bf16 u32s into
// frag-ordered g_hbf; staging is a contiguous 32KB copy. fp32 h state lives
// in finalizer registers (hp never re-read); g_hseq keeps fp32 for GEMMs.
// Barrier: R5 two-hop.
// ===========================================================================
struct ScanSmem {
    u32      bfrag[2][32][6][32][2];   // [hl][chunk][ntile][lane][2] 98304 B
    u32      afrag[2 * 32 * 32 * 4];   // [hl][chunk][lane][4]       32768 B
    float    red[512][26];             //                             53248 B
    float    bhs[48];
    unsigned baseu[2];
};

__global__ void __launch_bounds__(512, 1)
scan_kernel(const float* __restrict__ Whh, const float* __restrict__ bhh,
            const float* __restrict__ xp, float* __restrict__ hseq)
{
    extern __shared__ ScanSmem smem[];
    ScanSmem& s = smem[0];

    const int tid  = threadIdx.x;
    const int lane = tid & 31;
    const int ks   = tid >> 5;          // warp id: k-chunks 2ks, 2ks+1
    const int bt   = blockIdx.x >> 5;
    const int jt   = blockIdx.x & 31;
    const int b0   = bt * 16;
    const int j0   = jt * 16;

    if (tid == 0) {
        s.baseu[0] = ld_acq(&g_flags[bt][jt]);
        s.baseu[1] = ld_acq(&g_genf[bt][0]);
    }

    // ---- preamble: build B fragments from Whh (once)
    for (int i = tid; i < 32 * 6 * 32; i += 512) {
        const int ln = i & 31;
        const int n  = (i >> 5) % 6;
        const int c  = i / (6 * 32);
        const int g  = n >> 1;
        const int jj = (n & 1) * 8 + (ln >> 2);
        const int k  = c * 16 + (ln & 3) * 2;
        const float* wrow = Whh + (size_t)(g * H_SZ + j0 + jj) * H_SZ + k;
        float2 w0 = *(const float2*)(wrow);       // k, k+1
        float2 w1 = *(const float2*)(wrow + 8);   // k+8, k+9
        __nv_bfloat16 h0, l0, h1, l1, h2, l2, h3, l3;
        split_bf(w0.x, h0, l0); split_bf(w0.y, h1, l1);
        split_bf(w1.x, h2, l2); split_bf(w1.y, h3, l3);
        s.bfrag[0][c][n][ln][0] = pack_bf2(h0, h1);
        s.bfrag[0][c][n][ln][1] = pack_bf2(h2, h3);
        s.bfrag[1][c][n][ln][0] = pack_bf2(l0, l1);
        s.bfrag[1][c][n][ln][1] = pack_bf2(l2, l3);
    }
    if (tid < 48) s.bhs[tid] = bhh[(tid >> 4) * H_SZ + j0 + (tid & 15)];
    __syncthreads();

    const unsigned base_flag = s.baseu[0];
    const unsigned base_gen  = s.baseu[1];

    // Finalizer identity (tid < 128): 1 batch x 2 j each.
    const int fb   = tid >> 5;
    const int fi5  = tid & 31;
    const int fbg  = fi5 >> 3;
    const int fjg  = fi5 & 7;
    const int fbl  = fbg * 4 + fb;
    const int fjl0 = fjg * 2;
    const int lane_c = (fbl & 7) * 4 + (fjg & 3);
    const int coff   = (fbl >= 8) ? 2 : 0;
    // frag-ordered hbf offset for this finalizer's u32 (chunk = jt)
    const int hbf_off = jt * 128 + lane_c * 4 + ((fbl >= 8) ? 1 : 0) + ((fjg >= 4) ? 2 : 0);

    float2 hvp = make_float2(0.f, 0.f);   // fp32 recurrent state (this thread's)

    // xp prefetch for t = 0
    float2 xv[3];
    if (tid < 128) {
        const size_t row = ((size_t)(b0 + fbl) * T_SZ + 0) * G3_SZ;
#pragma unroll
        for (int g = 0; g < 3; g++)
            xv[g] = *(const float2*)(xp + row + g * H_SZ + j0 + fjl0);
    }

    for (int t = 0; t < T_SZ; t++) {
        // ---- stage A fragments (contiguous copy of frag-ordered g_hbf)
        if (t == 0) {
            const uint4 z = make_uint4(0u, 0u, 0u, 0u);
#pragma unroll
            for (int u = 0; u < 4; u++)
                *(uint4*)&s.afrag[u * 2048 + tid * 4] = z;
        } else {
            const u32* src = &g_hbf[bt][t - 1][0];
            uint4 v[4];
#pragma unroll
            for (int u = 0; u < 4; u++)
                v[u] = *(const uint4*)&src[u * 2048 + tid * 4];
#pragma unroll
            for (int u = 0; u < 4; u++)
                *(uint4*)&s.afrag[u * 2048 + tid * 4] = v[u];
        }
        __syncthreads();

        // ---- tensor dot: warp ks, chunks 2ks / 2ks+1
        float dacc[6][4];
#pragma unroll
        for (int n = 0; n < 6; n++)
#pragma unroll
            for (int c = 0; c < 4; c++) dacc[n][c] = 0.f;

        {
            const int c0 = 2 * ks;
#pragma unroll
            for (int cc = 0; cc < 2; cc++) {
                const int c = c0 + cc;
                u32 ah[4], al[4];
                *(uint4*)ah = *(const uint4*)&s.afrag[(0 * 32 + c) * 128 + lane * 4];
                *(uint4*)al = *(const uint4*)&s.afrag[(1 * 32 + c) * 128 + lane * 4];
#pragma unroll
                for (int n = 0; n < 6; n++) {
                    u32 bh[2], bl[2];
                    bh[0] = s.bfrag[0][c][n][lane][0];
                    bh[1] = s.bfrag[0][c][n][lane][1];
                    bl[0] = s.bfrag[1][c][n][lane][0];
                    bl[1] = s.bfrag[1][c][n][lane][1];
                    mma_bf16(dacc[n], ah, bh);
                    mma_bf16(dacc[n], ah, bl);
                    mma_bf16(dacc[n], al, bh);
                }
            }
        }

        // ---- write partials (12 STS.64, layout [ntile*4 + {0,2}])
        {
            float* rp = &s.red[tid][0];
#pragma unroll
            for (int n = 0; n < 6; n++) {
                *(float2*)(rp + n * 4)     = make_float2(dacc[n][0], dacc[n][1]);
                *(float2*)(rp + n * 4 + 2) = make_float2(dacc[n][2], dacc[n][3]);
            }
        }
        __syncthreads();

        // ---- finalize: tid < 128; sum 16 warps' C fragments, gates, stores
        if (tid < 128) {
            float2 tg[3];
#pragma unroll
            for (int g = 0; g < 3; g++) {
                const int r = g * 16 + fjl0;
                const int slot = (r >> 3) * 4 + coff;
                float2 sum = make_float2(0.f, 0.f);
#pragma unroll
                for (int w = 0; w < 16; w++) {
                    float2 v = *(const float2*)&s.red[w * 32 + lane_c][slot];
                    sum.x += v.x; sum.y += v.y;
                }
                tg[g] = sum;
            }
            float2 hv;
#pragma unroll
            for (int p = 0; p < 2; p++) {
                const int jl = fjl0 + p;
                float dr = (p == 0) ? tg[0].x : tg[0].y;
                float dz = (p == 0) ? tg[1].x : tg[1].y;
                float dn = (p == 0) ? tg[2].x : tg[2].y;
                float xr = (p == 0) ? xv[0].x : xv[0].y;
                float xz = (p == 0) ? xv[1].x : xv[1].y;
                float xn = (p == 0) ? xv[2].x : xv[2].y;
                float rg = 1.f / (1.f + __expf(-(xr + dr + s.bhs[jl])));
                float zg = 1.f / (1.f + __expf(-(xz + dz + s.bhs[16 + jl])));
                float ng = tanhf(xn + rg * (dn + s.bhs[32 + jl]));
                float hp = (p == 0) ? hvp.x : hvp.y;
                float h  = (1.f - zg) * ng + zg * hp;
                if (p == 0) hv.x = h; else hv.y = h;
            }
            hvp = hv;

            // fp32 h for GEMMs/head
            *(float2*)(hseq + ((size_t)(b0 + fbl) * T_SZ + t) * H_SZ + j0 + fjl0) = hv;
            // bf16 hi/lo A-fragment u32s (frag-ordered)
            __nv_bfloat16 xh, xl, yh, yl;
            split_bf(hv.x, xh, xl); split_bf(hv.y, yh, yl);
            u32* dst = &g_hbf[bt][t][0];
            dst[hbf_off]        = pack_bf2(xh, yh);
            dst[4096 + hbf_off] = pack_bf2(xl, yl);

            // prefetch xp for next step
            const int tn = (t + 1 < T_SZ) ? t + 1 : t;
            const size_t row = ((size_t)(b0 + fbl) * T_SZ + tn) * G3_SZ;
#pragma unroll
            for (int g = 0; g < 3; g++)
                xv[g] = *(const float2*)(xp + row + g * H_SZ + j0 + fjl0);
        }
        __syncthreads();

        // ---- two-hop group barrier (R5)
        {
            const unsigned tgt = base_flag + (unsigned)t + 1u;
            if (tid == 0) st_rel(&g_flags[bt][jt], tgt);
            if (jt == 0) {
                if (tid < 32) {
                    while ((int)(ld_acq(&g_flags[bt][tid]) - tgt) < 0) { }
                    __syncwarp();
                    if (tid == 0) st_rel(&g_genf[bt][0], base_gen + (unsigned)t + 1u);
                }
            } else if (tid == 0) {
                const unsigned gt = base_gen + (unsigned)t + 1u;
                while ((int)(ld_acq(&g_genf[bt][0]) - gt) < 0) { }
            }
        }
        __syncthreads();
    }
}

// ---------------------------------------------------------------------------
// Launch
// ---------------------------------------------------------------------------
extern "C" void kernel_launch(void* const* d_in, const int* in_sizes, int n_in,
                              void* d_out, int out_size)
{
    (void)in_sizes; (void)n_in; (void)out_size;
    const float* x    = (const float*)d_in[0];
    const float* Wih0 = (const float*)d_in[1];
    const float* Whh0 = (const float*)d_in[2];
    const float* bih0 = (const float*)d_in[3];
    const float* bhh0 = (const float*)d_in[4];
    const float* Wih1 = (const float*)d_in[5];
    const float* Whh1 = (const float*)d_in[6];
    const float* bih1 = (const float*)d_in[7];
    const float* bhh1 = (const float*)d_in[8];
    const float* Wih2 = (const float*)d_in[9];
    const float* Whh2 = (const float*)d_in[10];
    const float* bih2 = (const float*)d_in[11];
    const float* bhh2 = (const float*)d_in[12];
    const float* Wout = (const float*)d_in[13];
    const float* bout = (const float*)d_in[14];
    float* out = (float*)d_out;

    cudaFuncSetAttribute(scan_kernel, cudaFuncAttributeMaxDynamicSharedMemorySize,
                         (int)sizeof(ScanSmem));

    void *xp_v = nullptr, *hs_v = nullptr;
    cudaGetSymbolAddress(&xp_v, g_xp);
    cudaGetSymbolAddress(&hs_v, g_hseq);
    float* xpd = (float*)xp_v;
    float* hs  = (float*)hs_v;

    const dim3 tblk(256), sblk(512);
    const dim3 g_proj(G3_SZ / 128, M_SZ / 128);
    const dim3 g_head(O_SZ / 128,  M_SZ / 128);
    const size_t scan_smem = sizeof(ScanSmem);

    tgemm_kernel<<<g_proj, tblk>>>(x,  Wih0, bih0, xpd, M_SZ, G3_SZ, F_SZ);
    scan_kernel<<<SCAN_NBLK, sblk, scan_smem>>>(Whh0, bhh0, xpd, hs);
    tgemm_kernel<<<g_proj, tblk>>>(hs, Wih1, bih1, xpd, M_SZ, G3_SZ, H_SZ);
    scan_kernel<<<SCAN_NBLK, sblk, scan_smem>>>(Whh1, bhh1, xpd, hs);
    tgemm_kernel<<<g_proj, tblk>>>(hs, Wih2, bih2, xpd, M_SZ, G3_SZ, H_SZ);
    scan_kernel<<<SCAN_NBLK, sblk, scan_smem>>>(Whh2, bhh2, xpd, hs);
    tgemm_kernel<<<g_head, tblk>>>(hs, Wout, bout, out, M_SZ, O_SZ, H_SZ);
}